// round 11
// baseline (speedup 1.0000x reference)
#include <cuda_runtime.h>
#include <cuda_fp16.h>
#include <cstdint>

#define B_N   16
#define LATD  512
#define KSZ   147456
#define JTOT  147584

#define KS_CTAS   296
#define KS_WARPS  (KS_CTAS * 8)        // 2368
#define NB16      (JTOT / 16)          // 9224 j16 blocks

typedef unsigned long long ull;

// ---------------- persistent scratch ----------------
__device__ float   g_ks[(size_t)B_N * JTOT];
__device__ __half  g_k [(size_t)B_N * 9 * 128 * 128];   // [b][tap][co][ci] fp16
__device__ __half  g_xh[(size_t)B_N * 66 * 66 * 128];   // [b][pr][pc][ci] fp16, zero border

// ---------------- helpers ----------------
__device__ __forceinline__ uint32_t smem_u32(const void* p) {
    uint32_t a;
    asm("{ .reg .u64 t; cvta.to.shared.u64 t, %1; cvt.u32.u64 %0, t; }" : "=r"(a) : "l"(p));
    return a;
}
__device__ __forceinline__ void ldm4(uint32_t* r, uint32_t addr) {
    asm volatile("ldmatrix.sync.aligned.m8n8.x4.shared.b16 {%0,%1,%2,%3}, [%4];"
                 : "=r"(r[0]), "=r"(r[1]), "=r"(r[2]), "=r"(r[3]) : "r"(addr));
}
__device__ __forceinline__ void mma16816(float* c, const uint32_t* a, uint32_t b0, uint32_t b1) {
    asm volatile("mma.sync.aligned.m16n8k16.row.col.f32.f16.f16.f32 "
                 "{%0,%1,%2,%3}, {%4,%5,%6,%7}, {%8,%9}, {%0,%1,%2,%3};"
                 : "+f"(c[0]), "+f"(c[1]), "+f"(c[2]), "+f"(c[3])
                 : "r"(a[0]), "r"(a[1]), "r"(a[2]), "r"(a[3]), "r"(b0), "r"(b1));
}
__device__ __forceinline__ void cpa16(uint32_t d, const void* s) {
    asm volatile("cp.async.ca.shared.global [%0], [%1], 16;" :: "r"(d), "l"(s));
}
__device__ __forceinline__ uint32_t cvt2h(float lo, float hi) {
    uint32_t d;
    asm("cvt.rn.f16x2.f32 %0, %1, %2;" : "=r"(d) : "f"(hi), "f"(lo));
    return d;
}

// ---------------- kernel 1: ks = lat @ W.T + b  (persistent HMMA streaming) ----------------
// 296 CTAs (2/SM). afrag built once per CTA. Each warp strides over j16 blocks,
// two independent j8 accumulator chains per iteration for MLP.
__global__ void __launch_bounds__(256) ks_mma_kernel(const float* __restrict__ lat,
                                                     const float* __restrict__ W,
                                                     const float* __restrict__ bias) {
    __shared__ uint32_t afrag[2][32][32][4];   // [hl][ktile][lane][reg] = 32 KB
    const int t = threadIdx.x, lane = t & 31, w = t >> 5;

    // ---- build A fragments once (each warp: 4 k-tiles) ----
    {
        const int m = lane >> 2, kq = (lane & 3) * 2;
#pragma unroll
        for (int i = 0; i < 4; i++) {
            const int kt = w * 4 + i;
            const int k0 = kt * 16 + kq;
            const float v[8] = {
                lat[m * LATD + k0],       lat[m * LATD + k0 + 1],
                lat[(m + 8) * LATD + k0], lat[(m + 8) * LATD + k0 + 1],
                lat[m * LATD + k0 + 8],       lat[m * LATD + k0 + 9],
                lat[(m + 8) * LATD + k0 + 8], lat[(m + 8) * LATD + k0 + 9]
            };
#pragma unroll
            for (int r = 0; r < 4; r++) {
                const float lo = v[2 * r], hi = v[2 * r + 1];
                const uint32_t hf = cvt2h(lo, hi);
                afrag[0][kt][lane][r] = hf;
                const __half2 hv = *reinterpret_cast<const __half2*>(&hf);
                afrag[1][kt][lane][r] = cvt2h(lo - __low2float(hv), hi - __high2float(hv));
            }
        }
    }
    __syncthreads();

    const int wg   = blockIdx.x * 8 + w;
    const int rsel = lane >> 2;
    const int ksel = (lane & 3) * 2;
    const int jcol = (lane & 3) * 2;

    for (int blk = wg; blk < NB16; blk += KS_WARPS) {
        const int jb = blk * 16;
        const float* W0 = W + (size_t)(jb + rsel) * LATD + ksel;
        const float* W1 = W + (size_t)(jb + 8 + rsel) * LATD + ksel;

        float acc0[4] = {0.f, 0.f, 0.f, 0.f};
        float acc1[4] = {0.f, 0.f, 0.f, 0.f};
#pragma unroll 4
        for (int kt = 0; kt < 32; kt++) {
            const float2 a0 = *reinterpret_cast<const float2*>(W0 + kt * 16);
            const float2 a1 = *reinterpret_cast<const float2*>(W0 + kt * 16 + 8);
            const float2 c0 = *reinterpret_cast<const float2*>(W1 + kt * 16);
            const float2 c1 = *reinterpret_cast<const float2*>(W1 + kt * 16 + 8);
            const uint32_t fa0 = cvt2h(a0.x, a0.y), fa1 = cvt2h(a1.x, a1.y);
            const uint32_t fc0 = cvt2h(c0.x, c0.y), fc1 = cvt2h(c1.x, c1.y);
            const uint4 Ah = *reinterpret_cast<const uint4*>(&afrag[0][kt][lane][0]);
            const uint4 Al = *reinterpret_cast<const uint4*>(&afrag[1][kt][lane][0]);
            mma16816(acc0, reinterpret_cast<const uint32_t*>(&Ah), fa0, fa1);
            mma16816(acc1, reinterpret_cast<const uint32_t*>(&Ah), fc0, fc1);
            mma16816(acc0, reinterpret_cast<const uint32_t*>(&Al), fa0, fa1);
            mma16816(acc1, reinterpret_cast<const uint32_t*>(&Al), fc0, fc1);
        }

#pragma unroll
        for (int half = 0; half < 2; half++) {
            const float* ac = half ? acc1 : acc0;
            const int j0 = jb + half * 8 + jcol;
            const float2 bs = *reinterpret_cast<const float2*>(bias + j0);
            float2 o0 = make_float2(ac[0] + bs.x, ac[1] + bs.y);
            float2 o1 = make_float2(ac[2] + bs.x, ac[3] + bs.y);
            *reinterpret_cast<float2*>(g_ks + (size_t)rsel * JTOT + j0)       = o0;
            *reinterpret_cast<float2*>(g_ks + (size_t)(rsel + 8) * JTOT + j0) = o1;
        }
    }
}

// ---------------- kernel 2: kern -> [b][tap][co][ci] fp16, coalesced both sides ----------------
__global__ void __launch_bounds__(128) kcvt_kernel() {
    __shared__ float s[1152];
    const int b = blockIdx.y, co = blockIdx.x, t = threadIdx.x;
    const float* src = g_ks + (size_t)b * JTOT + (size_t)co * 1152;
    for (int i = t; i < 1152; i += 128) s[i] = src[i];
    __syncthreads();
#pragma unroll
    for (int tap = 0; tap < 9; tap++)
        g_k[(((size_t)b * 9 + tap) * 128 + co) * 128 + t] = __float2half(s[t * 9 + tap]);
}

// ---------------- kernel 3: transpose x -> padded [b][pr][pc][ci] fp16 ----------------
__global__ void __launch_bounds__(256) xsplit_kernel(const float* __restrict__ x) {
    __shared__ float s[128 * 65];
    const int b = blockIdx.y, r = blockIdx.x, t = threadIdx.x;
    const float* xb = x + (size_t)b * 128 * 4096 + (size_t)r * 64;
    for (int i = t; i < 128 * 64; i += 256) {
        int ci = i >> 6, c = i & 63;
        s[ci * 65 + c] = xb[(size_t)ci * 4096 + c];
    }
    __syncthreads();
    size_t obase = ((size_t)b * 66 + (r + 1)) * 66 * 128 + 128;
    for (int i = t; i < 128 * 64; i += 256) {
        int c = i >> 7, ci = i & 127;
        g_xh[obase + (size_t)c * 128 + ci] = __float2half(s[ci * 65 + c]);
    }
}

// ---------------- kernel 4: HMMA conv, single-pass fp16, cp.async double-buffered ----------------
#define A_PITCH 40
#define A_TILE  (128 * A_PITCH)
#define A_BUF   (3 * A_TILE)
#define B_ROW   (66 * A_PITCH)
#define B_BUF   (2 * B_ROW)
#define SMEM_BYTES ((2 * A_BUF + 2 * B_BUF) * 2)   // 82560

__global__ void __launch_bounds__(256, 2) conv_mma_kernel(float* __restrict__ y) {
    extern __shared__ __half sm[];
    const uint32_t as0 = smem_u32(sm);
    const uint32_t as1 = as0 + A_BUF * 2;
    const uint32_t bs0 = as0 + 2 * A_BUF * 2;
    const uint32_t bs1 = bs0 + B_BUF * 2;

    const int t = threadIdx.x, lane = t & 31, w = t >> 5;
    const int b = blockIdx.y, q = blockIdx.x;
    const int cog = w >> 2, posg = w & 3;
    const int rr_w = posg >> 1, c0w = (posg & 1) * 32;

    const int a_mrow = lane & 15;
    const int a_koff = (lane >= 16) ? 8 : 0;
    const int b_nrow = (lane & 7) + ((lane >= 16) ? 8 : 0);
    const int b_koff = ((lane >> 3) & 1) * 8;

    float acc[4][4][4];
#pragma unroll
    for (int mf = 0; mf < 4; mf++)
#pragma unroll
        for (int nf = 0; nf < 4; nf++)
#pragma unroll
            for (int e = 0; e < 4; e++) acc[mf][nf][e] = 0.f;

    auto stage = [&](uint32_t as_b, uint32_t bs_b, int kh, int cch) {
#pragma unroll
        for (int i = 0; i < 6; i++) {
            const int idx = t + i * 256;
            const int u = idx & 3, co = (idx >> 2) & 127, kw = idx >> 9;
            const __half* src = g_k +
                ((size_t)(b * 9 + kh * 3 + kw) * 16384 + (size_t)co * 128 + cch * 32 + u * 8);
            cpa16(as_b + (uint32_t)(kw * A_TILE + co * A_PITCH + u * 8) * 2, src);
        }
#pragma unroll
        for (int i = 0; i < 3; i++) {
            const int idx = t + i * 256;
            if (idx < 528) {
                const int u = idx & 3;
                const int pcr = idx >> 2;
                const int pc = pcr % 66, rr = pcr / 66;
                const __half* src = g_xh +
                    (((size_t)b * 66 + (q * 2 + rr + kh)) * 66 + pc) * 128 + cch * 32 + u * 8;
                cpa16(bs_b + (uint32_t)(rr * B_ROW + pc * A_PITCH + u * 8) * 2, src);
            }
        }
    };

    stage(as0, bs0, 0, 0);
    asm volatile("cp.async.commit_group;" ::: "memory");

#pragma unroll 1
    for (int s = 0; s < 12; s++) {
        const int buf = s & 1;
        if (s < 11) {
            const int sn = s + 1;
            stage(buf ? as0 : as1, buf ? bs0 : bs1, sn >> 2, sn & 3);
            asm volatile("cp.async.commit_group;" ::: "memory");
            asm volatile("cp.async.wait_group 1;" ::: "memory");
        } else {
            asm volatile("cp.async.wait_group 0;" ::: "memory");
        }
        __syncthreads();

        const uint32_t as_b = buf ? as1 : as0;
        const uint32_t bs_b = buf ? bs1 : bs0;
#pragma unroll
        for (int kw = 0; kw < 3; kw++) {
#pragma unroll
            for (int k16 = 0; k16 < 2; k16++) {
                const int k0 = k16 * 16;
                uint32_t Bh[8];
#pragma unroll
                for (int p = 0; p < 2; p++) {
                    const uint32_t ad = bs_b +
                        (uint32_t)(rr_w * B_ROW + (c0w + p * 16 + b_nrow + kw) * A_PITCH + k0 + b_koff) * 2;
                    ldm4(&Bh[p * 4], ad);
                }
#pragma unroll
                for (int mf = 0; mf < 4; mf++) {
                    uint32_t Ah[4];
                    const uint32_t aa = as_b +
                        (uint32_t)(kw * A_TILE + (cog * 64 + mf * 16 + a_mrow) * A_PITCH + k0 + a_koff) * 2;
                    ldm4(Ah, aa);
#pragma unroll
                    for (int nf = 0; nf < 4; nf++) {
                        const int bi = (nf >> 1) * 4 + (nf & 1) * 2;
                        mma16816(acc[mf][nf], Ah, Bh[bi], Bh[bi + 1]);
                    }
                }
            }
        }
        __syncthreads();
    }

    const int row_g = q * 2 + rr_w;
#pragma unroll
    for (int mf = 0; mf < 4; mf++) {
        const int co_a = cog * 64 + mf * 16 + (lane >> 2);
        const float bv0 = g_ks[(size_t)b * JTOT + KSZ + co_a];
        const float bv1 = g_ks[(size_t)b * JTOT + KSZ + co_a + 8];
        float* base0 = y + (((size_t)b * 128 + co_a) * 64 + row_g) * 64;
        float* base1 = y + (((size_t)b * 128 + co_a + 8) * 64 + row_g) * 64;
#pragma unroll
        for (int nf = 0; nf < 4; nf++) {
            const int col = c0w + nf * 8 + (lane & 3) * 2;
            float2 v0 = make_float2(acc[mf][nf][0] + bv0, acc[mf][nf][1] + bv0);
            float2 v1 = make_float2(acc[mf][nf][2] + bv1, acc[mf][nf][3] + bv1);
            *reinterpret_cast<float2*>(base0 + col) = v0;
            *reinterpret_cast<float2*>(base1 + col) = v1;
        }
    }
}

// ---------------- launch ----------------
extern "C" void kernel_launch(void* const* d_in, const int* in_sizes, int n_in,
                              void* d_out, int out_size) {
    const float* x    = (const float*)d_in[0];
    const float* lat  = (const float*)d_in[1];
    const float* W    = (const float*)d_in[2];
    const float* bias = (const float*)d_in[3];
    float* y = (float*)d_out;

    cudaFuncSetAttribute(conv_mma_kernel, cudaFuncAttributeMaxDynamicSharedMemorySize, SMEM_BYTES);

    ks_mma_kernel<<<KS_CTAS, 256>>>(lat, W, bias);
    kcvt_kernel<<<dim3(128, B_N), 128>>>();
    xsplit_kernel<<<dim3(64, B_N), 256>>>(x);
    conv_mma_kernel<<<dim3(32, B_N), 256, SMEM_BYTES>>>(y);
}

// round 12
// speedup vs baseline: 1.1518x; 1.1518x over previous
#include <cuda_runtime.h>
#include <cuda_fp16.h>
#include <cstdint>

#define B_N   16
#define LATD  512
#define KSZ   147456
#define JTOT  147584

#define KS_CTAS  148
#define NBLK     (JTOT / 64)        // 2306 j64 blocks
#define W_PITCH  136                // floats; conflict-free LDS.64 (8 banks apart per row)
#define W_STAGE  (64 * W_PITCH * 4) // 34816 bytes per stage
#define KS_DSMEM (3 * W_STAGE)      // 104448 dynamic smem (ring of 3)

// ---------------- persistent scratch ----------------
__device__ float   g_ks[(size_t)B_N * JTOT];            // bias region used by conv
__device__ __half  g_k [(size_t)B_N * 9 * 128 * 128];   // [b][tap][co][ci] fp16
__device__ __half  g_xh[(size_t)B_N * 66 * 66 * 128];   // [b][pr][pc][ci] fp16, zero border

// ---------------- helpers ----------------
__device__ __forceinline__ uint32_t smem_u32(const void* p) {
    uint32_t a;
    asm("{ .reg .u64 t; cvta.to.shared.u64 t, %1; cvt.u32.u64 %0, t; }" : "=r"(a) : "l"(p));
    return a;
}
__device__ __forceinline__ void ldm4(uint32_t* r, uint32_t addr) {
    asm volatile("ldmatrix.sync.aligned.m8n8.x4.shared.b16 {%0,%1,%2,%3}, [%4];"
                 : "=r"(r[0]), "=r"(r[1]), "=r"(r[2]), "=r"(r[3]) : "r"(addr));
}
__device__ __forceinline__ void mma16816(float* c, const uint32_t* a, uint32_t b0, uint32_t b1) {
    asm volatile("mma.sync.aligned.m16n8k16.row.col.f32.f16.f16.f32 "
                 "{%0,%1,%2,%3}, {%4,%5,%6,%7}, {%8,%9}, {%0,%1,%2,%3};"
                 : "+f"(c[0]), "+f"(c[1]), "+f"(c[2]), "+f"(c[3])
                 : "r"(a[0]), "r"(a[1]), "r"(a[2]), "r"(a[3]), "r"(b0), "r"(b1));
}
__device__ __forceinline__ void cpa16(uint32_t d, const void* s) {
    asm volatile("cp.async.ca.shared.global [%0], [%1], 16;" :: "r"(d), "l"(s));
}
__device__ __forceinline__ uint32_t cvt2h(float lo, float hi) {
    uint32_t d;
    asm("cvt.rn.f16x2.f32 %0, %1, %2;" : "=r"(d) : "f"(hi), "f"(lo));
    return d;
}

// ---------------- kernel 1: ks = lat @ W.T + b -> scatter fp16 to g_k ----------------
// 148 persistent CTAs. W streamed via 3-deep cp.async ring (memory decoupled from compute).
// A (lat) fp16 hi/lo fragments built once into static smem. Warp = one j8 chain.
__global__ void __launch_bounds__(256) ks_mma_kernel(const float* __restrict__ lat,
                                                     const float* __restrict__ W,
                                                     const float* __restrict__ bias) {
    __shared__ uint32_t afrag[2][32][32][4];   // 32 KB static
    extern __shared__ float wring[];           // 3 * 64 * 136 floats
    const uint32_t wbase = smem_u32(wring);

    const int t = threadIdx.x, lane = t & 31, w = t >> 5;
    const int bid = blockIdx.x;

    // ---- build A fragments once (each warp: 4 k-tiles) ----
    {
        const int m = lane >> 2, kq = (lane & 3) * 2;
#pragma unroll
        for (int i = 0; i < 4; i++) {
            const int kt = w * 4 + i;
            const int k0 = kt * 16 + kq;
            const float v[8] = {
                lat[m * LATD + k0],       lat[m * LATD + k0 + 1],
                lat[(m + 8) * LATD + k0], lat[(m + 8) * LATD + k0 + 1],
                lat[m * LATD + k0 + 8],       lat[m * LATD + k0 + 9],
                lat[(m + 8) * LATD + k0 + 8], lat[(m + 8) * LATD + k0 + 9]
            };
#pragma unroll
            for (int r = 0; r < 4; r++) {
                const float lo = v[2 * r], hi = v[2 * r + 1];
                const uint32_t hf = cvt2h(lo, hi);
                afrag[0][kt][lane][r] = hf;
                const __half2 hv = *reinterpret_cast<const __half2*>(&hf);
                afrag[1][kt][lane][r] = cvt2h(lo - __low2float(hv), hi - __high2float(hv));
            }
        }
    }
    __syncthreads();

    // number of blocks for this CTA, stages = nb*4
    const int nb = (NBLK - bid + KS_CTAS - 1) / KS_CTAS;
    const int T  = nb * 4;

    // stage issuer: stage index s -> (block i, k-chunk kc)
    auto issue = [&](int s) {
        const int i = s >> 2, kc = s & 3;
        const int blk = bid + i * KS_CTAS;
        const uint32_t buf = wbase + (uint32_t)(s % 3) * W_STAGE;
#pragma unroll
        for (int ch = 0; ch < 8; ch++) {
            const int idx = t + ch * 256;
            const int r = idx >> 5, c16 = idx & 31;
            cpa16(buf + (uint32_t)(r * (W_PITCH * 4) + c16 * 16),
                  W + (size_t)(blk * 64 + r) * LATD + kc * 128 + c16 * 4);
        }
        asm volatile("cp.async.commit_group;" ::: "memory");
    };

    const int rsel = lane >> 2;            // 0..7: row-in-j8 / batch
    const int ksel = (lane & 3) * 2;
    const int jcol = (lane & 3) * 2;

    issue(0);
    if (T > 1) issue(1);

    float acc[4] = {0.f, 0.f, 0.f, 0.f};

    for (int s = 0; s < T; s++) {
        if (s + 2 < T) { issue(s + 2); asm volatile("cp.async.wait_group 2;" ::: "memory"); }
        else if (s + 1 < T)            asm volatile("cp.async.wait_group 1;" ::: "memory");
        else                           asm volatile("cp.async.wait_group 0;" ::: "memory");
        __syncthreads();

        const int kc = s & 3;
        const float* wp = wring + (size_t)(s % 3) * (64 * W_PITCH)
                        + (w * 8 + rsel) * W_PITCH + ksel;
#pragma unroll
        for (int kt = 0; kt < 8; kt++) {
            const float2 w0 = *reinterpret_cast<const float2*>(wp + kt * 16);
            const float2 w1 = *reinterpret_cast<const float2*>(wp + kt * 16 + 8);
            const uint32_t b0 = cvt2h(w0.x, w0.y);
            const uint32_t b1 = cvt2h(w1.x, w1.y);
            const int kg = kc * 8 + kt;
            const uint4 Ah = *reinterpret_cast<const uint4*>(&afrag[0][kg][lane][0]);
            const uint4 Al = *reinterpret_cast<const uint4*>(&afrag[1][kg][lane][0]);
            mma16816(acc, reinterpret_cast<const uint32_t*>(&Ah), b0, b1);
            mma16816(acc, reinterpret_cast<const uint32_t*>(&Al), b0, b1);
        }
        __syncthreads();

        if (kc == 3) {
            // ---- epilogue: add bias, scatter fp16 into g_k (or fp32 bias into g_ks)
            const int blk = bid + (s >> 2) * KS_CTAS;
            const int j0 = blk * 64 + w * 8 + jcol;
            const float2 bs = *reinterpret_cast<const float2*>(bias + j0);
            const float vv[4] = {acc[0] + bs.x, acc[1] + bs.y, acc[2] + bs.x, acc[3] + bs.y};
#pragma unroll
            for (int e = 0; e < 4; e++) {
                const int bidx = (e < 2) ? rsel : (rsel + 8);
                const int j = j0 + (e & 1);
                if (j < KSZ) {
                    const int tap = j % 9, rem = j / 9;
                    const int ci = rem & 127, co = rem >> 7;
                    g_k[(((size_t)bidx * 9 + tap) * 128 + co) * 128 + ci] = __float2half(vv[e]);
                } else {
                    g_ks[(size_t)bidx * JTOT + j] = vv[e];
                }
            }
            acc[0] = acc[1] = acc[2] = acc[3] = 0.f;
        }
    }
}

// ---------------- kernel 2: transpose x -> padded [b][pr][pc][ci] fp16 ----------------
__global__ void __launch_bounds__(256) xsplit_kernel(const float* __restrict__ x) {
    __shared__ float s[128 * 65];
    const int b = blockIdx.y, r = blockIdx.x, t = threadIdx.x;
    const float* xb = x + (size_t)b * 128 * 4096 + (size_t)r * 64;
    for (int i = t; i < 128 * 64; i += 256) {
        int ci = i >> 6, c = i & 63;
        s[ci * 65 + c] = xb[(size_t)ci * 4096 + c];
    }
    __syncthreads();
    size_t obase = ((size_t)b * 66 + (r + 1)) * 66 * 128 + 128;
    for (int i = t; i < 128 * 64; i += 256) {
        int c = i >> 7, ci = i & 127;
        g_xh[obase + (size_t)c * 128 + ci] = __float2half(s[ci * 65 + c]);
    }
}

// ---------------- kernel 3: HMMA conv, single-pass fp16, cp.async double-buffered ----------------
#define A_PITCH 40
#define A_TILE  (128 * A_PITCH)
#define A_BUF   (3 * A_TILE)
#define B_ROW   (66 * A_PITCH)
#define B_BUF   (2 * B_ROW)
#define SMEM_BYTES ((2 * A_BUF + 2 * B_BUF) * 2)   // 82560

__global__ void __launch_bounds__(256, 2) conv_mma_kernel(float* __restrict__ y) {
    extern __shared__ __half sm[];
    const uint32_t as0 = smem_u32(sm);
    const uint32_t as1 = as0 + A_BUF * 2;
    const uint32_t bs0 = as0 + 2 * A_BUF * 2;
    const uint32_t bs1 = bs0 + B_BUF * 2;

    const int t = threadIdx.x, lane = t & 31, w = t >> 5;
    const int b = blockIdx.y, q = blockIdx.x;
    const int cog = w >> 2, posg = w & 3;
    const int rr_w = posg >> 1, c0w = (posg & 1) * 32;

    const int a_mrow = lane & 15;
    const int a_koff = (lane >= 16) ? 8 : 0;
    const int b_nrow = (lane & 7) + ((lane >= 16) ? 8 : 0);
    const int b_koff = ((lane >> 3) & 1) * 8;

    float acc[4][4][4];
#pragma unroll
    for (int mf = 0; mf < 4; mf++)
#pragma unroll
        for (int nf = 0; nf < 4; nf++)
#pragma unroll
            for (int e = 0; e < 4; e++) acc[mf][nf][e] = 0.f;

    auto stage = [&](uint32_t as_b, uint32_t bs_b, int kh, int cch) {
#pragma unroll
        for (int i = 0; i < 6; i++) {
            const int idx = t + i * 256;
            const int u = idx & 3, co = (idx >> 2) & 127, kw = idx >> 9;
            const __half* src = g_k +
                ((size_t)(b * 9 + kh * 3 + kw) * 16384 + (size_t)co * 128 + cch * 32 + u * 8);
            cpa16(as_b + (uint32_t)(kw * A_TILE + co * A_PITCH + u * 8) * 2, src);
        }
#pragma unroll
        for (int i = 0; i < 3; i++) {
            const int idx = t + i * 256;
            if (idx < 528) {
                const int u = idx & 3;
                const int pcr = idx >> 2;
                const int pc = pcr % 66, rr = pcr / 66;
                const __half* src = g_xh +
                    (((size_t)b * 66 + (q * 2 + rr + kh)) * 66 + pc) * 128 + cch * 32 + u * 8;
                cpa16(bs_b + (uint32_t)(rr * B_ROW + pc * A_PITCH + u * 8) * 2, src);
            }
        }
    };

    stage(as0, bs0, 0, 0);
    asm volatile("cp.async.commit_group;" ::: "memory");

#pragma unroll 1
    for (int s = 0; s < 12; s++) {
        const int buf = s & 1;
        if (s < 11) {
            const int sn = s + 1;
            stage(buf ? as0 : as1, buf ? bs0 : bs1, sn >> 2, sn & 3);
            asm volatile("cp.async.commit_group;" ::: "memory");
            asm volatile("cp.async.wait_group 1;" ::: "memory");
        } else {
            asm volatile("cp.async.wait_group 0;" ::: "memory");
        }
        __syncthreads();

        const uint32_t as_b = buf ? as1 : as0;
        const uint32_t bs_b = buf ? bs1 : bs0;
#pragma unroll
        for (int kw = 0; kw < 3; kw++) {
#pragma unroll
            for (int k16 = 0; k16 < 2; k16++) {
                const int k0 = k16 * 16;
                uint32_t Bh[8];
#pragma unroll
                for (int p = 0; p < 2; p++) {
                    const uint32_t ad = bs_b +
                        (uint32_t)(rr_w * B_ROW + (c0w + p * 16 + b_nrow + kw) * A_PITCH + k0 + b_koff) * 2;
                    ldm4(&Bh[p * 4], ad);
                }
#pragma unroll
                for (int mf = 0; mf < 4; mf++) {
                    uint32_t Ah[4];
                    const uint32_t aa = as_b +
                        (uint32_t)(kw * A_TILE + (cog * 64 + mf * 16 + a_mrow) * A_PITCH + k0 + a_koff) * 2;
                    ldm4(Ah, aa);
#pragma unroll
                    for (int nf = 0; nf < 4; nf++) {
                        const int bi = (nf >> 1) * 4 + (nf & 1) * 2;
                        mma16816(acc[mf][nf], Ah, Bh[bi], Bh[bi + 1]);
                    }
                }
            }
        }
        __syncthreads();
    }

    const int row_g = q * 2 + rr_w;
#pragma unroll
    for (int mf = 0; mf < 4; mf++) {
        const int co_a = cog * 64 + mf * 16 + (lane >> 2);
        const float bv0 = g_ks[(size_t)b * JTOT + KSZ + co_a];
        const float bv1 = g_ks[(size_t)b * JTOT + KSZ + co_a + 8];
        float* base0 = y + (((size_t)b * 128 + co_a) * 64 + row_g) * 64;
        float* base1 = y + (((size_t)b * 128 + co_a + 8) * 64 + row_g) * 64;
#pragma unroll
        for (int nf = 0; nf < 4; nf++) {
            const int col = c0w + nf * 8 + (lane & 3) * 2;
            float2 v0 = make_float2(acc[mf][nf][0] + bv0, acc[mf][nf][1] + bv0);
            float2 v1 = make_float2(acc[mf][nf][2] + bv1, acc[mf][nf][3] + bv1);
            *reinterpret_cast<float2*>(base0 + col) = v0;
            *reinterpret_cast<float2*>(base1 + col) = v1;
        }
    }
}

// ---------------- launch ----------------
extern "C" void kernel_launch(void* const* d_in, const int* in_sizes, int n_in,
                              void* d_out, int out_size) {
    const float* x    = (const float*)d_in[0];
    const float* lat  = (const float*)d_in[1];
    const float* W    = (const float*)d_in[2];
    const float* bias = (const float*)d_in[3];
    float* y = (float*)d_out;

    cudaFuncSetAttribute(ks_mma_kernel, cudaFuncAttributeMaxDynamicSharedMemorySize, KS_DSMEM);
    cudaFuncSetAttribute(conv_mma_kernel, cudaFuncAttributeMaxDynamicSharedMemorySize, SMEM_BYTES);

    ks_mma_kernel<<<KS_CTAS, 256, KS_DSMEM>>>(lat, W, bias);
    xsplit_kernel<<<dim3(64, B_N), 256>>>(x);
    conv_mma_kernel<<<dim3(32, B_N), 256, SMEM_BYTES>>>(y);
}

// round 13
// speedup vs baseline: 1.1996x; 1.0415x over previous
#include <cuda_runtime.h>
#include <cuda_fp16.h>
#include <cstdint>

#define B_N   16
#define LATD  512
#define KSZ   147456
#define JTOT  147584

#define KS_CTAS  148
#define NBLK     (JTOT / 64)        // 2306 j64 blocks
#define W_PITCH  136                // floats; conflict-free LDS.64
#define W_STAGE  (64 * W_PITCH * 4) // 34816 bytes per stage
#define KS_DSMEM (3 * W_STAGE)      // 104448 dynamic smem (ring of 3)

// ---------------- persistent scratch ----------------
__device__ float   g_ks[(size_t)B_N * JTOT];            // bias region used by conv
__device__ __half  g_k [(size_t)B_N * 9 * 128 * 128];   // [b][tap][co][ci] fp16
__device__ __half  g_xh[(size_t)B_N * 66 * 66 * 128];   // [b][pr][pc][ci] fp16, zero border

// ---------------- helpers ----------------
__device__ __forceinline__ uint32_t smem_u32(const void* p) {
    uint32_t a;
    asm("{ .reg .u64 t; cvta.to.shared.u64 t, %1; cvt.u32.u64 %0, t; }" : "=r"(a) : "l"(p));
    return a;
}
__device__ __forceinline__ void ldm4(uint32_t* r, uint32_t addr) {
    asm volatile("ldmatrix.sync.aligned.m8n8.x4.shared.b16 {%0,%1,%2,%3}, [%4];"
                 : "=r"(r[0]), "=r"(r[1]), "=r"(r[2]), "=r"(r[3]) : "r"(addr));
}
__device__ __forceinline__ void mma16816(float* c, const uint32_t* a, uint32_t b0, uint32_t b1) {
    asm volatile("mma.sync.aligned.m16n8k16.row.col.f32.f16.f16.f32 "
                 "{%0,%1,%2,%3}, {%4,%5,%6,%7}, {%8,%9}, {%0,%1,%2,%3};"
                 : "+f"(c[0]), "+f"(c[1]), "+f"(c[2]), "+f"(c[3])
                 : "r"(a[0]), "r"(a[1]), "r"(a[2]), "r"(a[3]), "r"(b0), "r"(b1));
}
__device__ __forceinline__ void cpa16(uint32_t d, const void* s) {
    asm volatile("cp.async.ca.shared.global [%0], [%1], 16;" :: "r"(d), "l"(s));
}
__device__ __forceinline__ uint32_t cvt2h(float lo, float hi) {
    uint32_t d;
    asm("cvt.rn.f16x2.f32 %0, %1, %2;" : "=r"(d) : "f"(hi), "f"(lo));
    return d;
}

// ---------------- kernel 1: ks = lat @ W.T + b -> scatter fp16 to g_k ----------------
// 148 persistent CTAs, 3-deep cp.async ring. lat fp16 single (error budget shared
// with W/x fp16 roundings). Per stage per warp: 16 LDS.64 + 8 LDS.128 + 16 cvt + 8 mma.
__global__ void __launch_bounds__(256) ks_mma_kernel(const float* __restrict__ lat,
                                                     const float* __restrict__ W,
                                                     const float* __restrict__ bias) {
    __shared__ uint32_t afrag[32][32][4];      // 16 KB static
    extern __shared__ float wring[];           // 3 * 64 * 136 floats
    const uint32_t wbase = smem_u32(wring);

    const int t = threadIdx.x, lane = t & 31, w = t >> 5;
    const int bid = blockIdx.x;

    // ---- build A fragments once (each warp: 4 k-tiles) ----
    {
        const int m = lane >> 2, kq = (lane & 3) * 2;
#pragma unroll
        for (int i = 0; i < 4; i++) {
            const int kt = w * 4 + i;
            const int k0 = kt * 16 + kq;
            afrag[kt][lane][0] = cvt2h(lat[m * LATD + k0],           lat[m * LATD + k0 + 1]);
            afrag[kt][lane][1] = cvt2h(lat[(m + 8) * LATD + k0],     lat[(m + 8) * LATD + k0 + 1]);
            afrag[kt][lane][2] = cvt2h(lat[m * LATD + k0 + 8],       lat[m * LATD + k0 + 9]);
            afrag[kt][lane][3] = cvt2h(lat[(m + 8) * LATD + k0 + 8], lat[(m + 8) * LATD + k0 + 9]);
        }
    }
    __syncthreads();

    const int nb = (NBLK - bid + KS_CTAS - 1) / KS_CTAS;
    const int T  = nb * 4;

    auto issue = [&](int s) {
        const int i = s >> 2, kc = s & 3;
        const int blk = bid + i * KS_CTAS;
        const uint32_t buf = wbase + (uint32_t)(s % 3) * W_STAGE;
#pragma unroll
        for (int ch = 0; ch < 8; ch++) {
            const int idx = t + ch * 256;
            const int r = idx >> 5, c16 = idx & 31;
            cpa16(buf + (uint32_t)(r * (W_PITCH * 4) + c16 * 16),
                  W + (size_t)(blk * 64 + r) * LATD + kc * 128 + c16 * 4);
        }
        asm volatile("cp.async.commit_group;" ::: "memory");
    };

    const int rsel = lane >> 2;
    const int ksel = (lane & 3) * 2;
    const int jcol = (lane & 3) * 2;

    issue(0);
    if (T > 1) issue(1);

    float acc[4] = {0.f, 0.f, 0.f, 0.f};

    for (int s = 0; s < T; s++) {
        if (s + 2 < T) { issue(s + 2); asm volatile("cp.async.wait_group 2;" ::: "memory"); }
        else if (s + 1 < T)            asm volatile("cp.async.wait_group 1;" ::: "memory");
        else                           asm volatile("cp.async.wait_group 0;" ::: "memory");
        __syncthreads();

        const int kc = s & 3;
        const float* wp = wring + (size_t)(s % 3) * (64 * W_PITCH)
                        + (w * 8 + rsel) * W_PITCH + ksel;
#pragma unroll
        for (int kt = 0; kt < 8; kt++) {
            const float2 w0 = *reinterpret_cast<const float2*>(wp + kt * 16);
            const float2 w1 = *reinterpret_cast<const float2*>(wp + kt * 16 + 8);
            const uint32_t b0 = cvt2h(w0.x, w0.y);
            const uint32_t b1 = cvt2h(w1.x, w1.y);
            const uint4 Ah = *reinterpret_cast<const uint4*>(&afrag[kc * 8 + kt][lane][0]);
            mma16816(acc, reinterpret_cast<const uint32_t*>(&Ah), b0, b1);
        }
        __syncthreads();

        if (kc == 3) {
            const int blk = bid + (s >> 2) * KS_CTAS;
            const int j0 = blk * 64 + w * 8 + jcol;
            const float2 bs = *reinterpret_cast<const float2*>(bias + j0);
            const float vv[4] = {acc[0] + bs.x, acc[1] + bs.y, acc[2] + bs.x, acc[3] + bs.y};
#pragma unroll
            for (int e = 0; e < 4; e++) {
                const int bidx = (e < 2) ? rsel : (rsel + 8);
                const int j = j0 + (e & 1);
                if (j < KSZ) {
                    const int tap = j % 9, rem = j / 9;
                    const int ci = rem & 127, co = rem >> 7;
                    g_k[(((size_t)bidx * 9 + tap) * 128 + co) * 128 + ci] = __float2half(vv[e]);
                } else {
                    g_ks[(size_t)bidx * JTOT + j] = vv[e];
                }
            }
            acc[0] = acc[1] = acc[2] = acc[3] = 0.f;
        }
    }
}

// ---------------- kernel 2: transpose x -> padded [b][pr][pc][ci] fp16 ----------------
__global__ void __launch_bounds__(256) xsplit_kernel(const float* __restrict__ x) {
    __shared__ float s[128 * 65];
    const int b = blockIdx.y, r = blockIdx.x, t = threadIdx.x;
    const float* xb = x + (size_t)b * 128 * 4096 + (size_t)r * 64;
    for (int i = t; i < 128 * 64; i += 256) {
        int ci = i >> 6, c = i & 63;
        s[ci * 65 + c] = xb[(size_t)ci * 4096 + c];
    }
    __syncthreads();
    size_t obase = ((size_t)b * 66 + (r + 1)) * 66 * 128 + 128;
    for (int i = t; i < 128 * 64; i += 256) {
        int c = i >> 7, ci = i & 127;
        g_xh[obase + (size_t)c * 128 + ci] = __float2half(s[ci * 65 + c]);
    }
}

// ---------------- kernel 3: HMMA conv, single-pass fp16, cp.async double-buffered ----------------
#define A_PITCH 40
#define A_TILE  (128 * A_PITCH)
#define A_BUF   (3 * A_TILE)
#define B_ROW   (66 * A_PITCH)
#define B_BUF   (2 * B_ROW)
#define SMEM_BYTES ((2 * A_BUF + 2 * B_BUF) * 2)   // 82560

__global__ void __launch_bounds__(256, 2) conv_mma_kernel(float* __restrict__ y) {
    extern __shared__ __half sm[];
    const uint32_t as0 = smem_u32(sm);
    const uint32_t as1 = as0 + A_BUF * 2;
    const uint32_t bs0 = as0 + 2 * A_BUF * 2;
    const uint32_t bs1 = bs0 + B_BUF * 2;

    const int t = threadIdx.x, lane = t & 31, w = t >> 5;
    const int b = blockIdx.y, q = blockIdx.x;
    const int cog = w >> 2, posg = w & 3;
    const int rr_w = posg >> 1, c0w = (posg & 1) * 32;

    const int a_mrow = lane & 15;
    const int a_koff = (lane >= 16) ? 8 : 0;
    const int b_nrow = (lane & 7) + ((lane >= 16) ? 8 : 0);
    const int b_koff = ((lane >> 3) & 1) * 8;

    float acc[4][4][4];
#pragma unroll
    for (int mf = 0; mf < 4; mf++)
#pragma unroll
        for (int nf = 0; nf < 4; nf++)
#pragma unroll
            for (int e = 0; e < 4; e++) acc[mf][nf][e] = 0.f;

    auto stage = [&](uint32_t as_b, uint32_t bs_b, int kh, int cch) {
#pragma unroll
        for (int i = 0; i < 6; i++) {
            const int idx = t + i * 256;
            const int u = idx & 3, co = (idx >> 2) & 127, kw = idx >> 9;
            const __half* src = g_k +
                ((size_t)(b * 9 + kh * 3 + kw) * 16384 + (size_t)co * 128 + cch * 32 + u * 8);
            cpa16(as_b + (uint32_t)(kw * A_TILE + co * A_PITCH + u * 8) * 2, src);
        }
#pragma unroll
        for (int i = 0; i < 3; i++) {
            const int idx = t + i * 256;
            if (idx < 528) {
                const int u = idx & 3;
                const int pcr = idx >> 2;
                const int pc = pcr % 66, rr = pcr / 66;
                const __half* src = g_xh +
                    (((size_t)b * 66 + (q * 2 + rr + kh)) * 66 + pc) * 128 + cch * 32 + u * 8;
                cpa16(bs_b + (uint32_t)(rr * B_ROW + pc * A_PITCH + u * 8) * 2, src);
            }
        }
    };

    stage(as0, bs0, 0, 0);
    asm volatile("cp.async.commit_group;" ::: "memory");

#pragma unroll 1
    for (int s = 0; s < 12; s++) {
        const int buf = s & 1;
        if (s < 11) {
            const int sn = s + 1;
            stage(buf ? as0 : as1, buf ? bs0 : bs1, sn >> 2, sn & 3);
            asm volatile("cp.async.commit_group;" ::: "memory");
            asm volatile("cp.async.wait_group 1;" ::: "memory");
        } else {
            asm volatile("cp.async.wait_group 0;" ::: "memory");
        }
        __syncthreads();

        const uint32_t as_b = buf ? as1 : as0;
        const uint32_t bs_b = buf ? bs1 : bs0;
#pragma unroll
        for (int kw = 0; kw < 3; kw++) {
#pragma unroll
            for (int k16 = 0; k16 < 2; k16++) {
                const int k0 = k16 * 16;
                uint32_t Bh[8];
#pragma unroll
                for (int p = 0; p < 2; p++) {
                    const uint32_t ad = bs_b +
                        (uint32_t)(rr_w * B_ROW + (c0w + p * 16 + b_nrow + kw) * A_PITCH + k0 + b_koff) * 2;
                    ldm4(&Bh[p * 4], ad);
                }
#pragma unroll
                for (int mf = 0; mf < 4; mf++) {
                    uint32_t Ah[4];
                    const uint32_t aa = as_b +
                        (uint32_t)(kw * A_TILE + (cog * 64 + mf * 16 + a_mrow) * A_PITCH + k0 + a_koff) * 2;
                    ldm4(Ah, aa);
#pragma unroll
                    for (int nf = 0; nf < 4; nf++) {
                        const int bi = (nf >> 1) * 4 + (nf & 1) * 2;
                        mma16816(acc[mf][nf], Ah, Bh[bi], Bh[bi + 1]);
                    }
                }
            }
        }
        __syncthreads();
    }

    const int row_g = q * 2 + rr_w;
#pragma unroll
    for (int mf = 0; mf < 4; mf++) {
        const int co_a = cog * 64 + mf * 16 + (lane >> 2);
        const float bv0 = g_ks[(size_t)b * JTOT + KSZ + co_a];
        const float bv1 = g_ks[(size_t)b * JTOT + KSZ + co_a + 8];
        float* base0 = y + (((size_t)b * 128 + co_a) * 64 + row_g) * 64;
        float* base1 = y + (((size_t)b * 128 + co_a + 8) * 64 + row_g) * 64;
#pragma unroll
        for (int nf = 0; nf < 4; nf++) {
            const int col = c0w + nf * 8 + (lane & 3) * 2;
            float2 v0 = make_float2(acc[mf][nf][0] + bv0, acc[mf][nf][1] + bv0);
            float2 v1 = make_float2(acc[mf][nf][2] + bv1, acc[mf][nf][3] + bv1);
            *reinterpret_cast<float2*>(base0 + col) = v0;
            *reinterpret_cast<float2*>(base1 + col) = v1;
        }
    }
}

// ---------------- launch ----------------
extern "C" void kernel_launch(void* const* d_in, const int* in_sizes, int n_in,
                              void* d_out, int out_size) {
    const float* x    = (const float*)d_in[0];
    const float* lat  = (const float*)d_in[1];
    const float* W    = (const float*)d_in[2];
    const float* bias = (const float*)d_in[3];
    float* y = (float*)d_out;

    cudaFuncSetAttribute(ks_mma_kernel, cudaFuncAttributeMaxDynamicSharedMemorySize, KS_DSMEM);
    cudaFuncSetAttribute(conv_mma_kernel, cudaFuncAttributeMaxDynamicSharedMemorySize, SMEM_BYTES);

    ks_mma_kernel<<<KS_CTAS, 256, KS_DSMEM>>>(lat, W, bias);
    xsplit_kernel<<<dim3(64, B_N), 256>>>(x);
    conv_mma_kernel<<<dim3(32, B_N), 256, SMEM_BYTES>>>(y);
}